// round 9
// baseline (speedup 1.0000x reference)
#include <cuda_runtime.h>
#include <cuda_fp16.h>
#include <float.h>
#include <math.h>
#include <cstdint>

#define BB 8
#define NN 2048
#define DD 512

// ---------------------------------------------------------------------------
// Scratch (__device__ globals only — allocation-free contract)
// ---------------------------------------------------------------------------
__device__ float g_xx[BB * NN];
__device__ float g_dist[(size_t)BB * NN * NN];          // 134 MB
__device__ __half g_sp[2][(size_t)BB * NN * DD];        // h / l fp16 splits, 32 MB

__device__ __forceinline__ uint32_t smem_u32(const void* p) {
    uint32_t a;
    asm("{ .reg .u64 t; cvta.to.shared.u64 t, %1; cvt.u32.u64 %0, t; }" : "=r"(a) : "l"(p));
    return a;
}

#define LDSM4(r0, r1, r2, r3, addr) \
    asm volatile("ldmatrix.sync.aligned.m8n8.x4.shared.b16 {%0,%1,%2,%3}, [%4];" \
                 : "=r"(r0), "=r"(r1), "=r"(r2), "=r"(r3) : "r"(addr))

#define MMA16816(c, a, b0, b1) \
    asm volatile("mma.sync.aligned.m16n8k16.row.col.f32.f16.f16.f32 " \
                 "{%0,%1,%2,%3}, {%4,%5,%6,%7}, {%8,%9}, {%0,%1,%2,%3};" \
                 : "+f"((c)[0]), "+f"((c)[1]), "+f"((c)[2]), "+f"((c)[3]) \
                 : "r"((a)[0]), "r"((a)[1]), "r"((a)[2]), "r"((a)[3]), "r"(b0), "r"(b1))

#define CP_ASYNC16(dst, src) \
    asm volatile("cp.async.cg.shared.global [%0], [%1], 16;" :: "r"(dst), "l"(src))
#define CP_COMMIT() asm volatile("cp.async.commit_group;" ::: "memory")

// ---------------------------------------------------------------------------
// Kernel 0: fp16 2-word split of put
// ---------------------------------------------------------------------------
__global__ __launch_bounds__(256) void split_kernel(const float* __restrict__ put) {
    size_t i4 = ((size_t)blockIdx.x * 256 + threadIdx.x) * 4;
    float4 v = *(const float4*)(put + i4);
    float x[4] = {v.x, v.y, v.z, v.w};
    __half h[4], l[4];
#pragma unroll
    for (int q = 0; q < 4; q++) {
        h[q] = __float2half(x[q]);
        l[q] = __float2half(x[q] - __half2float(h[q]));
    }
    *(uint2*)(&g_sp[0][i4]) = *(uint2*)h;
    *(uint2*)(&g_sp[1][i4]) = *(uint2*)l;
}

// ---------------------------------------------------------------------------
// Kernel 1: row squared norms (fp32 exact)
// ---------------------------------------------------------------------------
__global__ __launch_bounds__(256) void xx_kernel(const float* __restrict__ put) {
    int row  = blockIdx.x * 8 + (threadIdx.x >> 5);
    int lane = threadIdx.x & 31;
    const float* p = put + (size_t)row * DD;
    float s = 0.f;
#pragma unroll
    for (int f = 0; f < 4; f++) {
        float4 v = *(const float4*)(p + f * 128 + lane * 4);
        s = fmaf(v.x, v.x, s); s = fmaf(v.y, v.y, s);
        s = fmaf(v.z, v.z, s); s = fmaf(v.w, v.w, s);
    }
#pragma unroll
    for (int off = 16; off; off >>= 1) s += __shfl_xor_sync(0xffffffffu, s, off);
    if (lane == 0) g_xx[row] = s;
}

// ---------------------------------------------------------------------------
// Kernel 2: distance tiles — single launch (16,16,8). UNCHANGED (at roofline).
// ---------------------------------------------------------------------------
#define PITCH_H 40
#define TILE_B  (128 * PITCH_H * 2)
#define BUF_B   (4 * TILE_B)
#define XX_OFF  (2 * BUF_B)
#define SM_TOTAL (XX_OFF + 1024)
#define T_PITCH 136

__global__ __launch_bounds__(256, 1) void dist_mma_kernel() {
    int bx = blockIdx.x, by = blockIdx.y, b = blockIdx.z;
    if (by > bx) return;
    bool diag = (bx == by);

    extern __shared__ char smem[];
    uint32_t sbase = smem_u32(smem);
    int tid  = threadIdx.x;
    int lane = tid & 31;
    int wid  = tid >> 5;

    int j0 = by * 128, i0 = bx * 128, bofs = b * NN;

    float* xxA = (float*)(smem + XX_OFF);
    float* xxB = (float*)(smem + XX_OFF + 512);
    if (tid < 128) {
        xxA[tid] = g_xx[bofs + j0 + tid];
        xxB[tid] = g_xx[bofs + i0 + tid];
    }

    int fr   = (tid >> 2);
    int fck  = tid & 3;
    auto fill = [&](int buf, int kt) {
#pragma unroll
        for (int q = 0; q < 8; q++) {
            int rr   = fr + 64 * (q & 1);
            int tile = q >> 1;
            int word = tile & 1;
            int grow = (tile < 2 ? j0 : i0) + rr;
            const __half* src = &g_sp[word][(size_t)(bofs + grow) * DD + kt * 32 + fck * 8];
            uint32_t dst = sbase + buf * BUF_B + tile * TILE_B + rr * (PITCH_H * 2) + fck * 16;
            CP_ASYNC16(dst, src);
        }
    };

    int wm = (wid >> 2) * 64;
    int wn = (wid & 3) * 32;

    float acc[4][4][4];
#pragma unroll
    for (int im = 0; im < 4; im++)
#pragma unroll
        for (int in = 0; in < 4; in++)
#pragma unroll
            for (int q = 0; q < 4; q++) acc[im][in][q] = 0.f;

    fill(0, 0);
    CP_COMMIT();

    int arow = lane & 15;
    int acol = (lane >> 4) * 8;
    int brow = (lane & 7) + ((lane >> 4) << 3);
    int bcol = ((lane >> 3) & 1) * 8;

    for (int kt = 0; kt < 16; kt++) {
        if (kt < 15) { fill((kt + 1) & 1, kt + 1); CP_COMMIT(); }
        if (kt < 15) asm volatile("cp.async.wait_group 1;" ::: "memory");
        else         asm volatile("cp.async.wait_group 0;" ::: "memory");
        __syncthreads();

        uint32_t base = sbase + (kt & 1) * BUF_B;
#pragma unroll
        for (int kc = 0; kc < 2; kc++) {
            int kofs = kc * 16;
            uint32_t ah[4][4], al[4][4];
#pragma unroll
            for (int im = 0; im < 4; im++) {
                uint32_t off = (uint32_t)((wm + im * 16 + arow) * (PITCH_H * 2) + (kofs + acol) * 2);
                LDSM4(ah[im][0], ah[im][1], ah[im][2], ah[im][3], base + 0 * TILE_B + off);
                LDSM4(al[im][0], al[im][1], al[im][2], al[im][3], base + 1 * TILE_B + off);
            }
            uint32_t bh[8], bl[8];
#pragma unroll
            for (int bp = 0; bp < 2; bp++) {
                uint32_t off = (uint32_t)((wn + bp * 16 + brow) * (PITCH_H * 2) + (kofs + bcol) * 2);
                LDSM4(bh[bp*4+0], bh[bp*4+1], bh[bp*4+2], bh[bp*4+3], base + 2 * TILE_B + off);
                LDSM4(bl[bp*4+0], bl[bp*4+1], bl[bp*4+2], bl[bp*4+3], base + 3 * TILE_B + off);
            }
#pragma unroll
            for (int im = 0; im < 4; im++)
#pragma unroll
                for (int in = 0; in < 4; in++) {
                    MMA16816(acc[im][in], ah[im], bh[in*2], bh[in*2+1]);
                    MMA16816(acc[im][in], ah[im], bl[in*2], bl[in*2+1]);
                    MMA16816(acc[im][in], al[im], bh[in*2], bh[in*2+1]);
                }
        }
        __syncthreads();
    }

    float* smemT = (float*)smem;

#pragma unroll
    for (int im = 0; im < 4; im++) {
#pragma unroll
        for (int h2 = 0; h2 < 2; h2++) {
            int row = wm + im * 16 + (lane >> 2) + h2 * 8;
            float xj = xxA[row];
#pragma unroll
            for (int in = 0; in < 4; in++) {
                int n = wn + in * 8 + (lane & 3) * 2;
                float g0 = acc[im][in][h2 * 2 + 0];
                float g1 = acc[im][in][h2 * 2 + 1];
                float v0 = sqrtf(fmaxf((xj + xxB[n])     - 2.0f * g0, 0.0f));
                float v1 = sqrtf(fmaxf((xj + xxB[n + 1]) - 2.0f * g1, 0.0f));
                *(float2*)&g_dist[((size_t)(bofs + j0 + row)) * NN + i0 + n] = make_float2(v0, v1);
                if (!diag) {
                    smemT[(n)     * T_PITCH + row] = v0;
                    smemT[(n + 1) * T_PITCH + row] = v1;
                }
            }
        }
    }

    if (!diag) {
        __syncthreads();
#pragma unroll
        for (int q = 0; q < 16; q++) {
            int fid = tid + 256 * q;
            int nrow = fid >> 5, f4 = fid & 31;
            float4 val = *(float4*)&smemT[nrow * T_PITCH + f4 * 4];
            *(float4*)&g_dist[((size_t)(bofs + i0 + nrow)) * NN + j0 + f4 * 4] = val;
        }
    }
}

// ---------------------------------------------------------------------------
// Kernel 3: persistent top-16 radix select. Each block pipelines 16 rows:
// cp.async prefetch of row r+1 overlaps the select phases of row r.
// ---------------------------------------------------------------------------
#define CAND_CAP 512
#define ROWS_PER_BLK 16
// smem words: buf[2][2048] | h0[256] | h1[256] | cv[512] | ci[512]
//             sure[16] | widx[16] | scal[8]
#define TP_H0   4096
#define TP_H1   4352
#define TP_CV   4608
#define TP_CI   5120
#define TP_SURE 5632
#define TP_WIDX 5648
#define TP_SCAL 5664
#define TP_SMEM_BYTES ((TP_SCAL + 8) * 4)

__device__ __forceinline__ void cmin3(uint32_t& v, uint32_t& i, uint32_t& j,
                                      uint32_t v2, uint32_t i2, uint32_t j2) {
    if (v2 < v || (v2 == v && i2 < i)) { v = v2; i = i2; j = j2; }
}
__device__ __forceinline__ void cmin2(uint32_t& v, uint32_t& i, uint32_t v2, uint32_t i2) {
    if (v2 < v || (v2 == v && i2 < i)) { v = v2; i = i2; }
}

__global__ __launch_bounds__(256) void topk_pers_kernel(float* __restrict__ out) {
    extern __shared__ uint32_t sh[];
    const uint32_t FULL = 0xffffffffu;
    uint32_t* h0   = sh + TP_H0;
    uint32_t* h1   = sh + TP_H1;
    uint32_t* cv   = sh + TP_CV;
    uint32_t* ci   = sh + TP_CI;
    uint32_t* sure = sh + TP_SURE;
    uint32_t* widx = sh + TP_WIDX;
    uint32_t* scal = sh + TP_SCAL;   // 0:b0 1:c0 2:P 3:clt 4:nsure 5:ncand

    int tid  = threadIdx.x;
    int lane = tid & 31;
    int wid  = tid >> 5;
    size_t row0 = (size_t)blockIdx.x * ROWS_PER_BLK;
    uint32_t sbase = smem_u32(sh);

    // prefetch row 0 into buf[0]
    {
        const char* src = (const char*)(g_dist + row0 * NN);
        CP_ASYNC16(sbase + tid * 16,        src + tid * 16);
        CP_ASYNC16(sbase + 4096 + tid * 16, src + 4096 + tid * 16);
        CP_COMMIT();
    }

    for (int it = 0; it < ROWS_PER_BLK; it++) {
        asm volatile("cp.async.wait_group 0;" ::: "memory");
        __syncthreads();   // buffer ready AND previous iteration fully done

        uint32_t* buf = sh + (it & 1) * 2048;

        // prefetch next row into the other buffer (overlaps all phases below)
        if (it + 1 < ROWS_PER_BLK) {
            const char* src = (const char*)(g_dist + (row0 + it + 1) * NN);
            uint32_t dst = sbase + ((it + 1) & 1) * 8192 + tid * 16;
            CP_ASYNC16(dst,        src + tid * 16);
            CP_ASYNC16(dst + 4096, src + 4096 + tid * 16);
            CP_COMMIT();
        }

        // read this thread's 8 values; zero both hists + counters
        uint32_t v[8];
        {
            uint4 a = ((const uint4*)buf)[tid * 2];
            uint4 b = ((const uint4*)buf)[tid * 2 + 1];
            v[0] = a.x; v[1] = a.y; v[2] = a.z; v[3] = a.w;
            v[4] = b.x; v[5] = b.y; v[6] = b.z; v[7] = b.w;
        }
        h0[tid] = 0;
        h1[tid] = 0;
        if (tid == 0) { scal[4] = 0; scal[5] = 0; }
        __syncthreads();

        // level-0 hist (bits [31:24]), warp-aggregated
#pragma unroll
        for (int q = 0; q < 8; q++) {
            uint32_t bin = v[q] >> 24;
            uint32_t mk = __match_any_sync(FULL, bin);
            if (lane == __ffs(mk) - 1) atomicAdd(&h0[bin], __popc(mk));
        }
        __syncthreads();

        if (wid == 0) {
            uint32_t loc[8], s = 0;
#pragma unroll
            for (int i = 0; i < 8; i++) { loc[i] = h0[lane * 8 + i]; s += loc[i]; }
            uint32_t incl = s;
#pragma unroll
            for (int o = 1; o < 32; o <<= 1) {
                uint32_t t = __shfl_up_sync(FULL, incl, o);
                if (lane >= o) incl += t;
            }
            uint32_t run = incl - s;
#pragma unroll
            for (int i = 0; i < 8; i++) {
                if (run < 16u && 16u <= run + loc[i]) { scal[0] = lane * 8 + i; scal[1] = run; }
                run += loc[i];
            }
        }
        __syncthreads();
        uint32_t b0 = scal[0], c0 = scal[1];

        // level-1 hist (bits [23:16] where top byte == b0)
#pragma unroll
        for (int q = 0; q < 8; q++) {
            bool act = ((v[q] >> 24) == b0);
            uint32_t bin = act ? ((v[q] >> 16) & 255u) : (256u + lane);
            uint32_t mk = __match_any_sync(FULL, bin);
            if (act && lane == __ffs(mk) - 1) atomicAdd(&h1[bin], __popc(mk));
        }
        __syncthreads();

        if (wid == 0) {
            uint32_t k1 = 16u - c0;
            uint32_t loc[8], s = 0;
#pragma unroll
            for (int i = 0; i < 8; i++) { loc[i] = h1[lane * 8 + i]; s += loc[i]; }
            uint32_t incl = s;
#pragma unroll
            for (int o = 1; o < 32; o <<= 1) {
                uint32_t t = __shfl_up_sync(FULL, incl, o);
                if (lane >= o) incl += t;
            }
            uint32_t run = incl - s;
#pragma unroll
            for (int i = 0; i < 8; i++) {
                if (run < k1 && k1 <= run + loc[i]) {
                    scal[2] = (b0 << 8) | (uint32_t)(lane * 8 + i);
                    scal[3] = c0 + run;
                }
                run += loc[i];
            }
        }
        __syncthreads();
        uint32_t P = scal[2], clt = scal[3], m = 16u - clt;

        // gather sure (prefix < P) and candidates (prefix == P)
#pragma unroll
        for (int q = 0; q < 8; q++) {
            uint32_t hi = v[q] >> 16;
            if (hi < P) {
                uint32_t p = atomicAdd(&scal[4], 1u);
                sure[p] = tid * 8 + q;
            } else if (hi == P) {
                uint32_t p = atomicAdd(&scal[5], 1u);
                if (p < CAND_CAP) { cv[p] = v[q]; ci[p] = tid * 8 + q; }
            }
        }
        __syncthreads();

        // warp 0: stable-min rounds
        if (wid == 0) {
            uint32_t n = scal[5];
            if (n <= CAND_CAP) {
                for (uint32_t itr = 0; itr < m; itr++) {
                    uint32_t bv = FULL, bi = FULL, bj = FULL;
                    for (uint32_t j = lane; j < n; j += 32)
                        cmin3(bv, bi, bj, cv[j], ci[j], j);
#pragma unroll
                    for (int o = 16; o; o >>= 1) {
                        uint32_t ov = __shfl_down_sync(FULL, bv, o);
                        uint32_t oi = __shfl_down_sync(FULL, bi, o);
                        uint32_t oj = __shfl_down_sync(FULL, bj, o);
                        cmin3(bv, bi, bj, ov, oi, oj);
                    }
                    if (lane == 0) { widx[itr] = bi; cv[bj] = FULL; ci[bj] = FULL; }
                    __syncwarp();
                }
            } else {
                // fallback: scan the row buffer directly with tombstones
                for (uint32_t itr = 0; itr < m; itr++) {
                    uint32_t bv = FULL, bi = FULL;
                    for (int c = 0; c < 64; c++) {
                        uint32_t idx = c * 32 + lane;
                        uint32_t val = buf[idx];
                        if ((val >> 16) == P) cmin2(bv, bi, val, idx);
                    }
#pragma unroll
                    for (int o = 16; o; o >>= 1) {
                        uint32_t ov = __shfl_down_sync(FULL, bv, o);
                        uint32_t oi = __shfl_down_sync(FULL, bi, o);
                        cmin2(bv, bi, ov, oi);
                    }
                    bi = __shfl_sync(FULL, bi, 0);
                    if (lane == 0) { widx[itr] = bi; }
                    if (lane == 0) buf[bi] = FULL;
                    __syncwarp();
                }
            }
        }
        __syncthreads();

        // write output row: zero, barrier, scatter ones
        float* orow = out + (row0 + it) * NN;
        float4 z = make_float4(0.f, 0.f, 0.f, 0.f);
        ((float4*)orow)[tid * 2]     = z;
        ((float4*)orow)[tid * 2 + 1] = z;
        __syncthreads();
        if (tid < clt)                      orow[sure[tid]] = 1.0f;
        if (tid >= 32 && tid < 32 + m)      orow[widx[tid - 32]] = 1.0f;
    }
}

// ---------------------------------------------------------------------------
extern "C" void kernel_launch(void* const* d_in, const int* in_sizes, int n_in,
                              void* d_out, int out_size) {
    const float* put = (const float*)d_in[0];
    float* out = (float*)d_out;

    cudaFuncSetAttribute(dist_mma_kernel, cudaFuncAttributeMaxDynamicSharedMemorySize, SM_TOTAL);
    cudaFuncSetAttribute(topk_pers_kernel, cudaFuncAttributeMaxDynamicSharedMemorySize, TP_SMEM_BYTES);

    split_kernel<<<(BB * NN * DD) / (256 * 4), 256>>>(put);
    xx_kernel<<<(BB * NN) / 8, 256>>>(put);
    dist_mma_kernel<<<dim3(16, 16, BB), 256, SM_TOTAL>>>();
    topk_pers_kernel<<<(BB * NN) / ROWS_PER_BLK, 256, TP_SMEM_BYTES>>>(out);
}